// round 4
// baseline (speedup 1.0000x reference)
#include <cuda_runtime.h>
#include <cstdint>

#define BB 8
#define SS 2048
#define DM 1024
#define DH 64
#define M_TOT (BB*SS)   // 16384

// Scratch (device globals — no allocations allowed)
__device__ float g_q [M_TOT*DH];
__device__ float g_k [M_TOT*DH];
__device__ float g_v [M_TOT*DH];
__device__ float g_oh[M_TOT*DH];

typedef unsigned long long u64;

__device__ __forceinline__ u64 dup2(float x){
    u64 r; asm("mov.b64 %0, {%1, %1};" : "=l"(r) : "f"(x)); return r;
}
__device__ __forceinline__ u64 pack2(float a, float b){
    u64 r; asm("mov.b64 %0, {%1, %2};" : "=l"(r) : "f"(a), "f"(b)); return r;
}
__device__ __forceinline__ float2 unpack2(u64 v){
    float2 f; asm("mov.b64 {%0, %1}, %2;" : "=f"(f.x), "=f"(f.y) : "l"(v)); return f;
}
__device__ __forceinline__ void fma2(u64 &d, u64 a, u64 b){
    asm("fma.rn.f32x2 %0, %1, %2, %0;" : "+l"(d) : "l"(a), "l"(b));
}
__device__ __forceinline__ void mul2(u64 &d, u64 a){
    asm("mul.rn.f32x2 %0, %0, %1;" : "+l"(d) : "l"(a));
}

// ---------------------------------------------------------------------------
// Kernel 1: fused QKV projection, all three heads in one block.
// Y[m,n] = sum_d X[m,d]*W[n,d],  N = 192 (Q|K|V), BM = 128, BK = 32.
// grid = 128 (single wave), block = 512. Double-buffered smem, register-staged
// global loads. Thread tile: 4m (2 f32x2 pairs) x 12n.
// smem: Xs[2][32][132], Ws[2][32][196]  (~82 KB dynamic)
// ---------------------------------------------------------------------------
#define XBUF (32*132)
#define WBUF (32*196)

__global__ __launch_bounds__(512) void qkv_kernel(
    const float* __restrict__ X,
    const float* __restrict__ Wq,
    const float* __restrict__ Wk,
    const float* __restrict__ Wv)
{
    extern __shared__ float sm[];
    float* Xs[2] = { sm,            sm + XBUF };
    float* Ws[2] = { sm + 2*XBUF,   sm + 2*XBUF + WBUF };

    const int tid = threadIdx.x;
    const int m0  = blockIdx.x * 128;
    const int tx  = tid & 15;    // n block: n = tx*12 + j
    const int ty  = tid >> 4;    // m block: m = ty*4 + (pair)

    // staging registers
    float4 xr[2], wqr, wkr, wvr;
    const int xk4 = tid & 7;          // reused index pieces
    const int wn  = tid >> 3;         // 0..63 (for W loads)

    u64 acc[2][12];
    #pragma unroll
    for (int p = 0; p < 2; p++)
        #pragma unroll
        for (int j = 0; j < 12; j++) acc[p][j] = 0ULL;

    // ---- prologue: load chunk 0 ----
    {
        #pragma unroll
        for (int i = 0; i < 2; i++) {
            int lin = tid + i * 512;
            int k4 = lin & 7, m = lin >> 3;
            xr[i] = *(const float4*)&X[(size_t)(m0 + m) * DM + k4 * 4];
        }
        wqr = *(const float4*)&Wq[(size_t)wn * DM + xk4 * 4];
        wkr = *(const float4*)&Wk[(size_t)wn * DM + xk4 * 4];
        wvr = *(const float4*)&Wv[(size_t)wn * DM + xk4 * 4];
        // store into buf 0
        #pragma unroll
        for (int i = 0; i < 2; i++) {
            int lin = tid + i * 512;
            int k4 = lin & 7, m = lin >> 3;
            Xs[0][(k4*4+0)*132 + m] = xr[i].x;
            Xs[0][(k4*4+1)*132 + m] = xr[i].y;
            Xs[0][(k4*4+2)*132 + m] = xr[i].z;
            Xs[0][(k4*4+3)*132 + m] = xr[i].w;
        }
        Ws[0][(xk4*4+0)*196 + wn] = wqr.x;  Ws[0][(xk4*4+1)*196 + wn] = wqr.y;
        Ws[0][(xk4*4+2)*196 + wn] = wqr.z;  Ws[0][(xk4*4+3)*196 + wn] = wqr.w;
        Ws[0][(xk4*4+0)*196 + wn + 64] = wkr.x;  Ws[0][(xk4*4+1)*196 + wn + 64] = wkr.y;
        Ws[0][(xk4*4+2)*196 + wn + 64] = wkr.z;  Ws[0][(xk4*4+3)*196 + wn + 64] = wkr.w;
        Ws[0][(xk4*4+0)*196 + wn + 128] = wvr.x; Ws[0][(xk4*4+1)*196 + wn + 128] = wvr.y;
        Ws[0][(xk4*4+2)*196 + wn + 128] = wvr.z; Ws[0][(xk4*4+3)*196 + wn + 128] = wvr.w;
    }
    __syncthreads();

    int cur = 0;
    for (int c = 0; c < 32; c++) {
        // issue next chunk's global loads first (latency overlapped with compute)
        if (c < 31) {
            int kk = (c + 1) * 32;
            #pragma unroll
            for (int i = 0; i < 2; i++) {
                int lin = tid + i * 512;
                int k4 = lin & 7, m = lin >> 3;
                xr[i] = *(const float4*)&X[(size_t)(m0 + m) * DM + kk + k4 * 4];
            }
            wqr = *(const float4*)&Wq[(size_t)wn * DM + kk + xk4 * 4];
            wkr = *(const float4*)&Wk[(size_t)wn * DM + kk + xk4 * 4];
            wvr = *(const float4*)&Wv[(size_t)wn * DM + kk + xk4 * 4];
        }

        // compute on current buffer
        const float* Xb = Xs[cur];
        const float* Wb = Ws[cur];
        #pragma unroll 8
        for (int k = 0; k < 32; k++) {
            const u64* xp = (const u64*)&Xb[k*132 + ty*4];
            u64 a0 = xp[0], a1 = xp[1];
            const float* wp = &Wb[k*196 + tx*12];
            float4 w0 = *(const float4*)wp;
            float4 w1 = *(const float4*)(wp + 4);
            float4 w2 = *(const float4*)(wp + 8);
            u64 b0 = dup2(w0.x), b1 = dup2(w0.y), b2 = dup2(w0.z), b3 = dup2(w0.w);
            u64 b4 = dup2(w1.x), b5 = dup2(w1.y), b6 = dup2(w1.z), b7 = dup2(w1.w);
            u64 b8 = dup2(w2.x), b9 = dup2(w2.y), b10 = dup2(w2.z), b11 = dup2(w2.w);
            fma2(acc[0][0], a0, b0);  fma2(acc[0][1], a0, b1);  fma2(acc[0][2], a0, b2);
            fma2(acc[0][3], a0, b3);  fma2(acc[0][4], a0, b4);  fma2(acc[0][5], a0, b5);
            fma2(acc[0][6], a0, b6);  fma2(acc[0][7], a0, b7);  fma2(acc[0][8], a0, b8);
            fma2(acc[0][9], a0, b9);  fma2(acc[0][10], a0, b10); fma2(acc[0][11], a0, b11);
            fma2(acc[1][0], a1, b0);  fma2(acc[1][1], a1, b1);  fma2(acc[1][2], a1, b2);
            fma2(acc[1][3], a1, b3);  fma2(acc[1][4], a1, b4);  fma2(acc[1][5], a1, b5);
            fma2(acc[1][6], a1, b6);  fma2(acc[1][7], a1, b7);  fma2(acc[1][8], a1, b8);
            fma2(acc[1][9], a1, b9);  fma2(acc[1][10], a1, b10); fma2(acc[1][11], a1, b11);
        }

        // store next chunk into the other buffer
        if (c < 31) {
            int nb = cur ^ 1;
            #pragma unroll
            for (int i = 0; i < 2; i++) {
                int lin = tid + i * 512;
                int k4 = lin & 7, m = lin >> 3;
                Xs[nb][(k4*4+0)*132 + m] = xr[i].x;
                Xs[nb][(k4*4+1)*132 + m] = xr[i].y;
                Xs[nb][(k4*4+2)*132 + m] = xr[i].z;
                Xs[nb][(k4*4+3)*132 + m] = xr[i].w;
            }
            Ws[nb][(xk4*4+0)*196 + wn] = wqr.x;  Ws[nb][(xk4*4+1)*196 + wn] = wqr.y;
            Ws[nb][(xk4*4+2)*196 + wn] = wqr.z;  Ws[nb][(xk4*4+3)*196 + wn] = wqr.w;
            Ws[nb][(xk4*4+0)*196 + wn + 64] = wkr.x;  Ws[nb][(xk4*4+1)*196 + wn + 64] = wkr.y;
            Ws[nb][(xk4*4+2)*196 + wn + 64] = wkr.z;  Ws[nb][(xk4*4+3)*196 + wn + 64] = wkr.w;
            Ws[nb][(xk4*4+0)*196 + wn + 128] = wvr.x; Ws[nb][(xk4*4+1)*196 + wn + 128] = wvr.y;
            Ws[nb][(xk4*4+2)*196 + wn + 128] = wvr.z; Ws[nb][(xk4*4+3)*196 + wn + 128] = wvr.w;
            __syncthreads();
        }
        cur ^= 1;
    }

    // epilogue: route each n to g_q / g_k / g_v
    #pragma unroll
    for (int j = 0; j < 12; j++) {
        int n = tx * 12 + j;
        float* base = (n < 64) ? g_q : ((n < 128) ? g_k : g_v);
        int nn = n & 63;
        #pragma unroll
        for (int p = 0; p < 2; p++) {
            float2 v = unpack2(acc[p][j]);
            size_t m = (size_t)m0 + ty*4 + 2*p;
            base[m*DH + nn]       = v.x;
            base[(m+1)*DH + nn]   = v.y;
        }
    }
}

// ---------------------------------------------------------------------------
// Kernel 2: causal flash attention (d=64), fp32, online softmax.
// grid = (16, 8), block = 256.  BQ=64, key tiles of 64.
// Causal balance: block x handles q-tiles {x, 31-x} -> exactly 33 key-tile
// iterations per block. K/V double-buffered with register prefetch
// (2 syncthreads per key-tile instead of 3, global latency hidden).
// smem: Qs + Ks[2] + Vs[2] + Ps, each 64*68 floats (~102 KB dynamic).
// ---------------------------------------------------------------------------
#define ATILE (64*68)

__global__ __launch_bounds__(256) void attn_kernel()
{
    extern __shared__ float sm[];
    float* Qs    = sm;                    // [64 h][68 m]
    float* Ksb[2] = { sm + ATILE,   sm + 2*ATILE };  // [64 h][68 key]
    float* Vsb[2] = { sm + 3*ATILE, sm + 4*ATILE };  // [64 key][68 h]
    float* Ps    = sm + 5*ATILE;          // [64 key][68 m]

    const int b   = blockIdx.y;
    const int tid = threadIdx.x;
    const int tx  = tid & 15, ty = tid >> 4;

    const float* Qg = g_q  + (size_t)b * SS * DH;
    const float* Kg = g_k  + (size_t)b * SS * DH;
    const float* Vg = g_v  + (size_t)b * SS * DH;
    float*       Og = g_oh + (size_t)b * SS * DH;

    float4 krs[4], vrs[4];

    for (int pass = 0; pass < 2; pass++) {
        const int qt = (pass == 0) ? (int)blockIdx.x : (31 - (int)blockIdx.x);
        const int q0 = qt * 64;
        const int n_kt = qt + 1;   // causal: key tiles 0..qt

        __syncthreads();   // protect smem reuse across passes
        // Load Q tile transposed: Qs[h][m]
        #pragma unroll
        for (int i = 0; i < 4; i++) {
            int lin = tid + i * 256;
            int h4 = lin & 15, m = lin >> 4;
            float4 v = *(const float4*)&Qg[(size_t)(q0 + m) * DH + h4 * 4];
            Qs[(h4*4+0)*68 + m] = v.x;
            Qs[(h4*4+1)*68 + m] = v.y;
            Qs[(h4*4+2)*68 + m] = v.z;
            Qs[(h4*4+3)*68 + m] = v.w;
        }
        // Prologue: load K/V tile 0 into buffer 0
        #pragma unroll
        for (int i = 0; i < 4; i++) {
            int lin = tid + i * 256;
            int h4 = lin & 15, kk = lin >> 4;
            krs[i] = *(const float4*)&Kg[(size_t)kk * DH + h4 * 4];
            vrs[i] = *(const float4*)&Vg[(size_t)kk * DH + h4 * 4];
        }
        #pragma unroll
        for (int i = 0; i < 4; i++) {
            int lin = tid + i * 256;
            int h4 = lin & 15, kk = lin >> 4;
            Ksb[0][(h4*4+0)*68 + kk] = krs[i].x;
            Ksb[0][(h4*4+1)*68 + kk] = krs[i].y;
            Ksb[0][(h4*4+2)*68 + kk] = krs[i].z;
            Ksb[0][(h4*4+3)*68 + kk] = krs[i].w;
            *(float4*)&Vsb[0][kk*68 + h4*4] = vrs[i];
        }

        float mrow[4], lrow[4], corrv[4];
        u64 o2[2][4];
        #pragma unroll
        for (int i = 0; i < 4; i++) { mrow[i] = -1e30f; lrow[i] = 0.f; }
        #pragma unroll
        for (int i = 0; i < 2; i++)
            #pragma unroll
            for (int j = 0; j < 4; j++) o2[i][j] = 0ULL;

        __syncthreads();
        int cur = 0;

        for (int kt = 0; kt < n_kt; kt++) {
            const int k0 = kt * 64;

            // prefetch next K/V tile into registers (latency hidden by QK^T)
            if (kt + 1 < n_kt) {
                const int kn = k0 + 64;
                #pragma unroll
                for (int i = 0; i < 4; i++) {
                    int lin = tid + i * 256;
                    int h4 = lin & 15, kk = lin >> 4;
                    krs[i] = *(const float4*)&Kg[(size_t)(kn + kk) * DH + h4 * 4];
                    vrs[i] = *(const float4*)&Vg[(size_t)(kn + kk) * DH + h4 * 4];
                }
            }

            const float* Ks = Ksb[cur];
            const float* Vs = Vsb[cur];

            // ---- S = Q K^T (reduce over h) ----
            u64 s2[2][4];
            #pragma unroll
            for (int i = 0; i < 2; i++)
                #pragma unroll
                for (int j = 0; j < 4; j++) s2[i][j] = 0ULL;
            #pragma unroll 8
            for (int h = 0; h < 64; h++) {
                const u64* qp = (const u64*)&Qs[h*68 + ty*4];
                u64 a0 = qp[0], a1 = qp[1];
                float4 kv = *(const float4*)&Ks[h*68 + tx*4];
                u64 b0 = dup2(kv.x), b1 = dup2(kv.y), b2 = dup2(kv.z), b3 = dup2(kv.w);
                fma2(s2[0][0], a0, b0); fma2(s2[0][1], a0, b1); fma2(s2[0][2], a0, b2); fma2(s2[0][3], a0, b3);
                fma2(s2[1][0], a1, b0); fma2(s2[1][1], a1, b1); fma2(s2[1][2], a1, b2); fma2(s2[1][3], a1, b3);
            }

            // unpack, scale 1/sqrt(1024), causal mask
            float p[4][4];
            #pragma unroll
            for (int i2 = 0; i2 < 2; i2++)
                #pragma unroll
                for (int j = 0; j < 4; j++) {
                    float2 v = unpack2(s2[i2][j]);
                    p[2*i2  ][j] = v.x;
                    p[2*i2+1][j] = v.y;
                }
            #pragma unroll
            for (int i = 0; i < 4; i++) {
                int q = q0 + ty*4 + i;
                #pragma unroll
                for (int j = 0; j < 4; j++) {
                    int kidx = k0 + tx*4 + j;
                    p[i][j] = (kidx <= q) ? p[i][j] * 0.03125f : -1e30f;
                }
            }

            // online softmax (row spread across 16 tx-lanes of warp half)
            #pragma unroll
            for (int i = 0; i < 4; i++) {
                float r = fmaxf(fmaxf(p[i][0], p[i][1]), fmaxf(p[i][2], p[i][3]));
                r = fmaxf(r, __shfl_xor_sync(0xffffffffu, r, 1, 16));
                r = fmaxf(r, __shfl_xor_sync(0xffffffffu, r, 2, 16));
                r = fmaxf(r, __shfl_xor_sync(0xffffffffu, r, 4, 16));
                r = fmaxf(r, __shfl_xor_sync(0xffffffffu, r, 8, 16));
                float mnew = fmaxf(mrow[i], r);
                float corr = __expf(mrow[i] - mnew);
                mrow[i] = mnew;
                float lsum = 0.f;
                #pragma unroll
                for (int j = 0; j < 4; j++) {
                    p[i][j] = __expf(p[i][j] - mnew);
                    lsum += p[i][j];
                }
                lsum += __shfl_xor_sync(0xffffffffu, lsum, 1, 16);
                lsum += __shfl_xor_sync(0xffffffffu, lsum, 2, 16);
                lsum += __shfl_xor_sync(0xffffffffu, lsum, 4, 16);
                lsum += __shfl_xor_sync(0xffffffffu, lsum, 8, 16);
                lrow[i] = lrow[i] * corr + lsum;
                corrv[i] = corr;
            }
            // rescale O accumulators
            #pragma unroll
            for (int i2 = 0; i2 < 2; i2++) {
                u64 c2 = pack2(corrv[2*i2], corrv[2*i2+1]);
                #pragma unroll
                for (int j = 0; j < 4; j++) mul2(o2[i2][j], c2);
            }
            // store P tile: Ps[key][m]
            #pragma unroll
            for (int i = 0; i < 4; i++) {
                int m = ty*4 + i;
                #pragma unroll
                for (int j = 0; j < 4; j++)
                    Ps[(tx*4 + j)*68 + m] = p[i][j];
            }
            // store prefetched K/V into the other buffer
            if (kt + 1 < n_kt) {
                float* Kn = Ksb[cur ^ 1];
                float* Vn = Vsb[cur ^ 1];
                #pragma unroll
                for (int i = 0; i < 4; i++) {
                    int lin = tid + i * 256;
                    int h4 = lin & 15, kk = lin >> 4;
                    Kn[(h4*4+0)*68 + kk] = krs[i].x;
                    Kn[(h4*4+1)*68 + kk] = krs[i].y;
                    Kn[(h4*4+2)*68 + kk] = krs[i].z;
                    Kn[(h4*4+3)*68 + kk] = krs[i].w;
                    *(float4*)&Vn[kk*68 + h4*4] = vrs[i];
                }
            }
            __syncthreads();   // Ps + next K/V ready

            // ---- O += P V (reduce over keys) ----
            #pragma unroll 8
            for (int kk = 0; kk < 64; kk++) {
                const u64* pp = (const u64*)&Ps[kk*68 + ty*4];
                u64 a0 = pp[0], a1 = pp[1];
                float4 vv = *(const float4*)&Vs[kk*68 + tx*4];
                u64 b0 = dup2(vv.x), b1 = dup2(vv.y), b2 = dup2(vv.z), b3 = dup2(vv.w);
                fma2(o2[0][0], a0, b0); fma2(o2[0][1], a0, b1); fma2(o2[0][2], a0, b2); fma2(o2[0][3], a0, b3);
                fma2(o2[1][0], a1, b0); fma2(o2[1][1], a1, b1); fma2(o2[1][2], a1, b2); fma2(o2[1][3], a1, b3);
            }
            __syncthreads();   // PV done before next Ps overwrite
            cur ^= 1;
        }

        // epilogue: divide by l, write O_head
        #pragma unroll
        for (int i2 = 0; i2 < 2; i2++) {
            u64 c2 = pack2(1.f / lrow[2*i2], 1.f / lrow[2*i2+1]);
            float2 r0, r1, r2, r3;
            mul2(o2[i2][0], c2); r0 = unpack2(o2[i2][0]);
            mul2(o2[i2][1], c2); r1 = unpack2(o2[i2][1]);
            mul2(o2[i2][2], c2); r2 = unpack2(o2[i2][2]);
            mul2(o2[i2][3], c2); r3 = unpack2(o2[i2][3]);
            size_t m = (size_t)q0 + ty*4 + 2*i2;
            *(float4*)&Og[m*DH + tx*4]     = make_float4(r0.x, r1.x, r2.x, r3.x);
            *(float4*)&Og[(m+1)*DH + tx*4] = make_float4(r0.y, r1.y, r2.y, r3.y);
        }
    }
}

// ---------------------------------------------------------------------------
// Kernel 3: output projection. out[m,d] = sum_h Oh[m,h] * Wo[d,h]
// grid = (256, 4), block = 256.  BM=64, BN=256, K=64 full.
// Wide BN cuts g_oh re-reads 16x -> 4x (L2 traffic 1.07GB -> 268MB).
// Thread tile 8m (4 f32x2 pairs) x 8d.  smem: Os[64][68] + Ws2[64][260] ~82KB.
// ---------------------------------------------------------------------------
__global__ __launch_bounds__(256) void oproj_kernel(
    const float* __restrict__ Wo, float* __restrict__ out)
{
    extern __shared__ float sm[];
    float* Os  = sm;            // [64 h][68 m]
    float* Ws2 = sm + 64*68;    // [64 h][260 d]

    const int m0 = blockIdx.x * 64;
    const int d0 = blockIdx.y * 256;
    const int tid = threadIdx.x;
    const int tx = tid & 31;    // d = d0 + tx*8 + j
    const int ty = tid >> 5;    // m = m0 + ty*8 + r

    // Load Oh tile transposed: Os[h][m]
    #pragma unroll
    for (int i = 0; i < 4; i++) {
        int lin = tid + i * 256;
        int h4 = lin & 15, r = lin >> 4;
        float4 v = *(const float4*)&g_oh[(size_t)(m0 + r) * DH + h4 * 4];
        Os[(h4*4+0)*68 + r] = v.x;
        Os[(h4*4+1)*68 + r] = v.y;
        Os[(h4*4+2)*68 + r] = v.z;
        Os[(h4*4+3)*68 + r] = v.w;
    }
    // Load Wo tile transposed: Ws2[h][d] (256 rows)
    #pragma unroll
    for (int i = 0; i < 16; i++) {
        int lin = tid + i * 256;
        int h4 = lin & 15, r = lin >> 4;
        float4 w = *(const float4*)&Wo[(size_t)(d0 + r) * DH + h4 * 4];
        Ws2[(h4*4+0)*260 + r] = w.x;
        Ws2[(h4*4+1)*260 + r] = w.y;
        Ws2[(h4*4+2)*260 + r] = w.z;
        Ws2[(h4*4+3)*260 + r] = w.w;
    }
    __syncthreads();

    u64 acc[4][8];
    #pragma unroll
    for (int p = 0; p < 4; p++)
        #pragma unroll
        for (int j = 0; j < 8; j++) acc[p][j] = 0ULL;

    #pragma unroll 8
    for (int h = 0; h < 64; h++) {
        const u64* op = (const u64*)&Os[h*68 + ty*8];
        u64 a0 = op[0], a1 = op[1], a2 = op[2], a3 = op[3];
        const float* wp = &Ws2[h*260 + tx*8];
        float4 w0 = *(const float4*)wp;
        float4 w1 = *(const float4*)(wp + 4);
        u64 b0 = dup2(w0.x), b1 = dup2(w0.y), b2 = dup2(w0.z), b3 = dup2(w0.w);
        u64 b4 = dup2(w1.x), b5 = dup2(w1.y), b6 = dup2(w1.z), b7 = dup2(w1.w);
        fma2(acc[0][0], a0, b0); fma2(acc[0][1], a0, b1); fma2(acc[0][2], a0, b2); fma2(acc[0][3], a0, b3);
        fma2(acc[0][4], a0, b4); fma2(acc[0][5], a0, b5); fma2(acc[0][6], a0, b6); fma2(acc[0][7], a0, b7);
        fma2(acc[1][0], a1, b0); fma2(acc[1][1], a1, b1); fma2(acc[1][2], a1, b2); fma2(acc[1][3], a1, b3);
        fma2(acc[1][4], a1, b4); fma2(acc[1][5], a1, b5); fma2(acc[1][6], a1, b6); fma2(acc[1][7], a1, b7);
        fma2(acc[2][0], a2, b0); fma2(acc[2][1], a2, b1); fma2(acc[2][2], a2, b2); fma2(acc[2][3], a2, b3);
        fma2(acc[2][4], a2, b4); fma2(acc[2][5], a2, b5); fma2(acc[2][6], a2, b6); fma2(acc[2][7], a2, b7);
        fma2(acc[3][0], a3, b0); fma2(acc[3][1], a3, b1); fma2(acc[3][2], a3, b2); fma2(acc[3][3], a3, b3);
        fma2(acc[3][4], a3, b4); fma2(acc[3][5], a3, b5); fma2(acc[3][6], a3, b6); fma2(acc[3][7], a3, b7);
    }

    #pragma unroll
    for (int p = 0; p < 4; p++) {
        float2 v0 = unpack2(acc[p][0]), v1 = unpack2(acc[p][1]);
        float2 v2 = unpack2(acc[p][2]), v3 = unpack2(acc[p][3]);
        float2 v4 = unpack2(acc[p][4]), v5 = unpack2(acc[p][5]);
        float2 v6 = unpack2(acc[p][6]), v7 = unpack2(acc[p][7]);
        size_t m = (size_t)m0 + ty*8 + 2*p;
        float* o0 = &out[m*DM + d0 + tx*8];
        float* o1 = &out[(m+1)*DM + d0 + tx*8];
        *(float4*)o0       = make_float4(v0.x, v1.x, v2.x, v3.x);
        *(float4*)(o0 + 4) = make_float4(v4.x, v5.x, v6.x, v7.x);
        *(float4*)o1       = make_float4(v0.y, v1.y, v2.y, v3.y);
        *(float4*)(o1 + 4) = make_float4(v4.y, v5.y, v6.y, v7.y);
    }
}

// ---------------------------------------------------------------------------
extern "C" void kernel_launch(void* const* d_in, const int* in_sizes, int n_in,
                              void* d_out, int out_size)
{
    const float* X  = (const float*)d_in[0];
    const float* Wq = (const float*)d_in[1];
    const float* Wk = (const float*)d_in[2];
    const float* Wv = (const float*)d_in[3];
    const float* Wo = (const float*)d_in[4];
    float* out = (float*)d_out;

    const int qkv_smem   = (2*XBUF + 2*WBUF) * (int)sizeof(float);   // ~82 KB
    const int attn_smem  = 6 * ATILE * (int)sizeof(float);           // ~102 KB
    const int oproj_smem = (64*68 + 64*260) * (int)sizeof(float);    // ~82 KB

    cudaFuncSetAttribute(qkv_kernel,   cudaFuncAttributeMaxDynamicSharedMemorySize, qkv_smem);
    cudaFuncSetAttribute(attn_kernel,  cudaFuncAttributeMaxDynamicSharedMemorySize, attn_smem);
    cudaFuncSetAttribute(oproj_kernel, cudaFuncAttributeMaxDynamicSharedMemorySize, oproj_smem);

    qkv_kernel<<<128, 512, qkv_smem>>>(X, Wq, Wk, Wv);
    attn_kernel<<<dim3(16, 8), 256, attn_smem>>>();
    oproj_kernel<<<dim3(256, 4), 256, oproj_smem>>>(Wo, out);
}

// round 5
// speedup vs baseline: 1.0616x; 1.0616x over previous
#include <cuda_runtime.h>
#include <cstdint>

#define BB 8
#define SS 2048
#define DM 1024
#define DH 64
#define M_TOT (BB*SS)   // 16384

// Scratch (device globals — no allocations allowed)
__device__ float g_q [M_TOT*DH];
__device__ float g_k [M_TOT*DH];
__device__ float g_v [M_TOT*DH];
__device__ float g_oh[M_TOT*DH];

typedef unsigned long long u64;

__device__ __forceinline__ u64 dup2(float x){
    u64 r; asm("mov.b64 %0, {%1, %1};" : "=l"(r) : "f"(x)); return r;
}
__device__ __forceinline__ u64 pack2(float a, float b){
    u64 r; asm("mov.b64 %0, {%1, %2};" : "=l"(r) : "f"(a), "f"(b)); return r;
}
__device__ __forceinline__ float2 unpack2(u64 v){
    float2 f; asm("mov.b64 {%0, %1}, %2;" : "=f"(f.x), "=f"(f.y) : "l"(v)); return f;
}
__device__ __forceinline__ void fma2(u64 &d, u64 a, u64 b){
    asm("fma.rn.f32x2 %0, %1, %2, %0;" : "+l"(d) : "l"(a), "l"(b));
}
__device__ __forceinline__ void mul2(u64 &d, u64 a){
    asm("mul.rn.f32x2 %0, %0, %1;" : "+l"(d) : "l"(a));
}

// ---------------------------------------------------------------------------
// Kernel 1: QKV projection.  Y[m,n] = sum_d X[m,d] * W[n,d]
// grid = (128, 3), block = 128 (4+ CTAs/SM for inter-CTA overlap).
// BM=128, BN=64, BK=32.  Thread tile 8m x 8n, accumulators f32x2-packed
// along n: B pairs load directly as u64 from smem (no MOV dup on B side).
// ---------------------------------------------------------------------------
__global__ __launch_bounds__(128, 4) void qkv_kernel(
    const float* __restrict__ X,
    const float* __restrict__ Wq,
    const float* __restrict__ Wk,
    const float* __restrict__ Wv)
{
    __shared__ float Xs[32*132];   // [k][m], stride 132 (528B = 33*16, aligned)
    __shared__ float Wsh[32*68];   // [k][n], stride 68  (272B = 17*16, aligned)

    const float* W = (blockIdx.y == 0) ? Wq : ((blockIdx.y == 1) ? Wk : Wv);
    float* Y = (blockIdx.y == 0) ? g_q : ((blockIdx.y == 1) ? g_k : g_v);

    const int tid = threadIdx.x;
    const int m0  = blockIdx.x * 128;
    const int tx  = tid & 7;    // n group: n = tx*8 + (2*np + lohi)
    const int ty  = tid >> 3;   // m group: m = ty*8 + i

    u64 acc[8][4];   // [m 0..7][n-pair 0..3], pair = (n, n+1)
    #pragma unroll
    for (int i = 0; i < 8; i++)
        #pragma unroll
        for (int j = 0; j < 4; j++) acc[i][j] = 0ULL;

    for (int kk = 0; kk < DM; kk += 32) {
        // X tile: 128m x 32k.  1024 float4 / 128 thr = 8 each.
        #pragma unroll
        for (int it = 0; it < 8; it++) {
            int lin = tid + it * 128;
            int k4 = lin & 7, m = lin >> 3;
            float4 v = *(const float4*)&X[(size_t)(m0 + m) * DM + kk + k4 * 4];
            Xs[(k4*4+0)*132 + m] = v.x;
            Xs[(k4*4+1)*132 + m] = v.y;
            Xs[(k4*4+2)*132 + m] = v.z;
            Xs[(k4*4+3)*132 + m] = v.w;
        }
        // W tile: 64n x 32k.  512 float4 / 128 thr = 4 each.
        #pragma unroll
        for (int it = 0; it < 4; it++) {
            int lin = tid + it * 128;
            int k4 = lin & 7, n = lin >> 3;
            float4 v = *(const float4*)&W[(size_t)n * DM + kk + k4 * 4];
            Wsh[(k4*4+0)*68 + n] = v.x;
            Wsh[(k4*4+1)*68 + n] = v.y;
            Wsh[(k4*4+2)*68 + n] = v.z;
            Wsh[(k4*4+3)*68 + n] = v.w;
        }
        __syncthreads();
        #pragma unroll 8
        for (int k = 0; k < 32; k++) {
            // B side: 4 u64 pairs, direct (2x LDS.128)
            const u64* bp = (const u64*)&Wsh[k*68 + tx*8];
            u64 b0 = bp[0], b1 = bp[1], b2 = bp[2], b3 = bp[3];
            // A side: 8 m floats (2x LDS.128) + dup
            float4 xa = *(const float4*)&Xs[k*132 + ty*8];
            float4 xb = *(const float4*)&Xs[k*132 + ty*8 + 4];
            u64 a0 = dup2(xa.x), a1 = dup2(xa.y), a2 = dup2(xa.z), a3 = dup2(xa.w);
            u64 a4 = dup2(xb.x), a5 = dup2(xb.y), a6 = dup2(xb.z), a7 = dup2(xb.w);
            fma2(acc[0][0], a0, b0); fma2(acc[0][1], a0, b1); fma2(acc[0][2], a0, b2); fma2(acc[0][3], a0, b3);
            fma2(acc[1][0], a1, b0); fma2(acc[1][1], a1, b1); fma2(acc[1][2], a1, b2); fma2(acc[1][3], a1, b3);
            fma2(acc[2][0], a2, b0); fma2(acc[2][1], a2, b1); fma2(acc[2][2], a2, b2); fma2(acc[2][3], a2, b3);
            fma2(acc[3][0], a3, b0); fma2(acc[3][1], a3, b1); fma2(acc[3][2], a3, b2); fma2(acc[3][3], a3, b3);
            fma2(acc[4][0], a4, b0); fma2(acc[4][1], a4, b1); fma2(acc[4][2], a4, b2); fma2(acc[4][3], a4, b3);
            fma2(acc[5][0], a5, b0); fma2(acc[5][1], a5, b1); fma2(acc[5][2], a5, b2); fma2(acc[5][3], a5, b3);
            fma2(acc[6][0], a6, b0); fma2(acc[6][1], a6, b1); fma2(acc[6][2], a6, b2); fma2(acc[6][3], a6, b3);
            fma2(acc[7][0], a7, b0); fma2(acc[7][1], a7, b1); fma2(acc[7][2], a7, b2); fma2(acc[7][3], a7, b3);
        }
        __syncthreads();
    }
    // epilogue: n-pairs are contiguous -> clean float4 stores
    #pragma unroll
    for (int i = 0; i < 8; i++) {
        float2 v0 = unpack2(acc[i][0]), v1 = unpack2(acc[i][1]);
        float2 v2 = unpack2(acc[i][2]), v3 = unpack2(acc[i][3]);
        size_t m = (size_t)m0 + ty*8 + i;
        float* yp = &Y[m*DH + tx*8];
        *(float4*)yp       = make_float4(v0.x, v0.y, v1.x, v1.y);
        *(float4*)(yp + 4) = make_float4(v2.x, v2.y, v3.x, v3.y);
    }
}

// ---------------------------------------------------------------------------
// Kernel 2: causal flash attention (d=64), fp32, online softmax.
// grid = (16, 8), block = 256.  BQ=64, key tiles of 64.
// Causal balance: block x handles q-tiles {x, 31-x} -> exactly 33 key-tile
// iterations per block (perfectly balanced single wave).  [R3 version]
// ---------------------------------------------------------------------------
__global__ __launch_bounds__(256) void attn_kernel()
{
    extern __shared__ float sm[];
    float* Qs = sm;                 // [64 h][68 m]
    float* Ks = Qs + 64*68;         // [64 h][68 key]
    float* Vs = Ks + 64*68;         // [64 key][68 h]
    float* Ps = Vs + 64*68;         // [64 key][68 m]

    const int b   = blockIdx.y;
    const int tid = threadIdx.x;
    const int tx  = tid & 15, ty = tid >> 4;

    const float* Qg = g_q  + (size_t)b * SS * DH;
    const float* Kg = g_k  + (size_t)b * SS * DH;
    const float* Vg = g_v  + (size_t)b * SS * DH;
    float*       Og = g_oh + (size_t)b * SS * DH;

    #pragma unroll
    for (int pass = 0; pass < 2; pass++) {
        const int qt = (pass == 0) ? (int)blockIdx.x : (31 - (int)blockIdx.x);
        const int q0 = qt * 64;

        __syncthreads();   // protect smem reuse across passes
        // Load Q tile transposed: Qs[h][m]
        #pragma unroll
        for (int i = 0; i < 4; i++) {
            int lin = tid + i * 256;
            int h4 = lin & 15, m = lin >> 4;
            float4 v = *(const float4*)&Qg[(size_t)(q0 + m) * DH + h4 * 4];
            Qs[(h4*4+0)*68 + m] = v.x;
            Qs[(h4*4+1)*68 + m] = v.y;
            Qs[(h4*4+2)*68 + m] = v.z;
            Qs[(h4*4+3)*68 + m] = v.w;
        }

        float mrow[4], lrow[4], corrv[4];
        u64 o2[2][4];
        #pragma unroll
        for (int i = 0; i < 4; i++) { mrow[i] = -1e30f; lrow[i] = 0.f; }
        #pragma unroll
        for (int i = 0; i < 2; i++)
            #pragma unroll
            for (int j = 0; j < 4; j++) o2[i][j] = 0ULL;

        const int n_kt = qt + 1;   // causal: keys up to q0+63
        for (int kt = 0; kt < n_kt; kt++) {
            const int k0 = kt * 64;
            __syncthreads();
            // K transposed (Ks[h][key]) + V direct (Vs[key][h])
            #pragma unroll
            for (int i = 0; i < 4; i++) {
                int lin = tid + i * 256;
                int h4 = lin & 15, kk = lin >> 4;
                float4 v = *(const float4*)&Kg[(size_t)(k0 + kk) * DH + h4 * 4];
                Ks[(h4*4+0)*68 + kk] = v.x;
                Ks[(h4*4+1)*68 + kk] = v.y;
                Ks[(h4*4+2)*68 + kk] = v.z;
                Ks[(h4*4+3)*68 + kk] = v.w;
                float4 w = *(const float4*)&Vg[(size_t)(k0 + kk) * DH + h4 * 4];
                *(float4*)&Vs[kk*68 + h4*4] = w;
            }
            __syncthreads();

            // ---- S = Q K^T (reduce over h). keys: 4*tx..4*tx+3, rows: ty*4..ty*4+3
            u64 s2[2][4];
            #pragma unroll
            for (int i = 0; i < 2; i++)
                #pragma unroll
                for (int j = 0; j < 4; j++) s2[i][j] = 0ULL;
            #pragma unroll 8
            for (int h = 0; h < 64; h++) {
                const u64* qp = (const u64*)&Qs[h*68 + ty*4];
                u64 a0 = qp[0], a1 = qp[1];
                float4 kv = *(const float4*)&Ks[h*68 + tx*4];
                u64 b0 = dup2(kv.x), b1 = dup2(kv.y), b2 = dup2(kv.z), b3 = dup2(kv.w);
                fma2(s2[0][0], a0, b0); fma2(s2[0][1], a0, b1); fma2(s2[0][2], a0, b2); fma2(s2[0][3], a0, b3);
                fma2(s2[1][0], a1, b0); fma2(s2[1][1], a1, b1); fma2(s2[1][2], a1, b2); fma2(s2[1][3], a1, b3);
            }

            // unpack, scale 1/sqrt(1024), causal mask
            float p[4][4];
            #pragma unroll
            for (int i2 = 0; i2 < 2; i2++)
                #pragma unroll
                for (int j = 0; j < 4; j++) {
                    float2 v = unpack2(s2[i2][j]);
                    p[2*i2  ][j] = v.x;
                    p[2*i2+1][j] = v.y;
                }
            #pragma unroll
            for (int i = 0; i < 4; i++) {
                int q = q0 + ty*4 + i;
                #pragma unroll
                for (int j = 0; j < 4; j++) {
                    int kidx = k0 + tx*4 + j;
                    p[i][j] = (kidx <= q) ? p[i][j] * 0.03125f : -1e30f;
                }
            }

            // online softmax (row spread across 16 tx-lanes of the warp half)
            #pragma unroll
            for (int i = 0; i < 4; i++) {
                float r = fmaxf(fmaxf(p[i][0], p[i][1]), fmaxf(p[i][2], p[i][3]));
                r = fmaxf(r, __shfl_xor_sync(0xffffffffu, r, 1, 16));
                r = fmaxf(r, __shfl_xor_sync(0xffffffffu, r, 2, 16));
                r = fmaxf(r, __shfl_xor_sync(0xffffffffu, r, 4, 16));
                r = fmaxf(r, __shfl_xor_sync(0xffffffffu, r, 8, 16));
                float mnew = fmaxf(mrow[i], r);
                float corr = __expf(mrow[i] - mnew);
                mrow[i] = mnew;
                float lsum = 0.f;
                #pragma unroll
                for (int j = 0; j < 4; j++) {
                    p[i][j] = __expf(p[i][j] - mnew);
                    lsum += p[i][j];
                }
                lsum += __shfl_xor_sync(0xffffffffu, lsum, 1, 16);
                lsum += __shfl_xor_sync(0xffffffffu, lsum, 2, 16);
                lsum += __shfl_xor_sync(0xffffffffu, lsum, 4, 16);
                lsum += __shfl_xor_sync(0xffffffffu, lsum, 8, 16);
                lrow[i] = lrow[i] * corr + lsum;
                corrv[i] = corr;
            }
            // rescale O accumulators (packed pairs along m)
            #pragma unroll
            for (int i2 = 0; i2 < 2; i2++) {
                u64 c2 = pack2(corrv[2*i2], corrv[2*i2+1]);
                #pragma unroll
                for (int j = 0; j < 4; j++) mul2(o2[i2][j], c2);
            }
            // store P tile: Ps[key][m]
            #pragma unroll
            for (int i = 0; i < 4; i++) {
                int m = ty*4 + i;
                #pragma unroll
                for (int j = 0; j < 4; j++)
                    Ps[(tx*4 + j)*68 + m] = p[i][j];
            }
            __syncthreads();

            // ---- O += P V (reduce over keys) ----
            #pragma unroll 8
            for (int kk = 0; kk < 64; kk++) {
                const u64* pp = (const u64*)&Ps[kk*68 + ty*4];
                u64 a0 = pp[0], a1 = pp[1];
                float4 vv = *(const float4*)&Vs[kk*68 + tx*4];
                u64 b0 = dup2(vv.x), b1 = dup2(vv.y), b2 = dup2(vv.z), b3 = dup2(vv.w);
                fma2(o2[0][0], a0, b0); fma2(o2[0][1], a0, b1); fma2(o2[0][2], a0, b2); fma2(o2[0][3], a0, b3);
                fma2(o2[1][0], a1, b0); fma2(o2[1][1], a1, b1); fma2(o2[1][2], a1, b2); fma2(o2[1][3], a1, b3);
            }
        }

        // epilogue: divide by l, write O_head
        #pragma unroll
        for (int i2 = 0; i2 < 2; i2++) {
            u64 c2 = pack2(1.f / lrow[2*i2], 1.f / lrow[2*i2+1]);
            float2 r0, r1, r2, r3;
            mul2(o2[i2][0], c2); r0 = unpack2(o2[i2][0]);
            mul2(o2[i2][1], c2); r1 = unpack2(o2[i2][1]);
            mul2(o2[i2][2], c2); r2 = unpack2(o2[i2][2]);
            mul2(o2[i2][3], c2); r3 = unpack2(o2[i2][3]);
            size_t m = (size_t)q0 + ty*4 + 2*i2;
            *(float4*)&Og[m*DH + tx*4]     = make_float4(r0.x, r1.x, r2.x, r3.x);
            *(float4*)&Og[(m+1)*DH + tx*4] = make_float4(r0.y, r1.y, r2.y, r3.y);
        }
    }
}

// ---------------------------------------------------------------------------
// Kernel 3: output projection. out[m,d] = sum_h Oh[m,h] * Wo[d,h]
// grid = (256, 4), block = 256.  BM=64, BN=256, K=64 full.
// Wide BN cuts g_oh re-reads 16x -> 4x.
// ---------------------------------------------------------------------------
__global__ __launch_bounds__(256) void oproj_kernel(
    const float* __restrict__ Wo, float* __restrict__ out)
{
    extern __shared__ float sm[];
    float* Os  = sm;            // [64 h][68 m]
    float* Ws2 = sm + 64*68;    // [64 h][260 d]

    const int m0 = blockIdx.x * 64;
    const int d0 = blockIdx.y * 256;
    const int tid = threadIdx.x;
    const int tx = tid & 31;    // d = d0 + tx*8 + j
    const int ty = tid >> 5;    // m = m0 + ty*8 + r

    // Load Oh tile transposed: Os[h][m]
    #pragma unroll
    for (int i = 0; i < 4; i++) {
        int lin = tid + i * 256;
        int h4 = lin & 15, r = lin >> 4;
        float4 v = *(const float4*)&g_oh[(size_t)(m0 + r) * DH + h4 * 4];
        Os[(h4*4+0)*68 + r] = v.x;
        Os[(h4*4+1)*68 + r] = v.y;
        Os[(h4*4+2)*68 + r] = v.z;
        Os[(h4*4+3)*68 + r] = v.w;
    }
    // Load Wo tile transposed: Ws2[h][d] (256 rows)
    #pragma unroll
    for (int i = 0; i < 16; i++) {
        int lin = tid + i * 256;
        int h4 = lin & 15, r = lin >> 4;
        float4 w = *(const float4*)&Wo[(size_t)(d0 + r) * DH + h4 * 4];
        Ws2[(h4*4+0)*260 + r] = w.x;
        Ws2[(h4*4+1)*260 + r] = w.y;
        Ws2[(h4*4+2)*260 + r] = w.z;
        Ws2[(h4*4+3)*260 + r] = w.w;
    }
    __syncthreads();

    u64 acc[4][8];
    #pragma unroll
    for (int p = 0; p < 4; p++)
        #pragma unroll
        for (int j = 0; j < 8; j++) acc[p][j] = 0ULL;

    #pragma unroll 8
    for (int h = 0; h < 64; h++) {
        const u64* op = (const u64*)&Os[h*68 + ty*8];
        u64 a0 = op[0], a1 = op[1], a2 = op[2], a3 = op[3];
        const float* wp = &Ws2[h*260 + tx*8];
        float4 w0 = *(const float4*)wp;
        float4 w1 = *(const float4*)(wp + 4);
        u64 b0 = dup2(w0.x), b1 = dup2(w0.y), b2 = dup2(w0.z), b3 = dup2(w0.w);
        u64 b4 = dup2(w1.x), b5 = dup2(w1.y), b6 = dup2(w1.z), b7 = dup2(w1.w);
        fma2(acc[0][0], a0, b0); fma2(acc[0][1], a0, b1); fma2(acc[0][2], a0, b2); fma2(acc[0][3], a0, b3);
        fma2(acc[0][4], a0, b4); fma2(acc[0][5], a0, b5); fma2(acc[0][6], a0, b6); fma2(acc[0][7], a0, b7);
        fma2(acc[1][0], a1, b0); fma2(acc[1][1], a1, b1); fma2(acc[1][2], a1, b2); fma2(acc[1][3], a1, b3);
        fma2(acc[1][4], a1, b4); fma2(acc[1][5], a1, b5); fma2(acc[1][6], a1, b6); fma2(acc[1][7], a1, b7);
        fma2(acc[2][0], a2, b0); fma2(acc[2][1], a2, b1); fma2(acc[2][2], a2, b2); fma2(acc[2][3], a2, b3);
        fma2(acc[2][4], a2, b4); fma2(acc[2][5], a2, b5); fma2(acc[2][6], a2, b6); fma2(acc[2][7], a2, b7);
        fma2(acc[3][0], a3, b0); fma2(acc[3][1], a3, b1); fma2(acc[3][2], a3, b2); fma2(acc[3][3], a3, b3);
        fma2(acc[3][4], a3, b4); fma2(acc[3][5], a3, b5); fma2(acc[3][6], a3, b6); fma2(acc[3][7], a3, b7);
    }

    #pragma unroll
    for (int p = 0; p < 4; p++) {
        float2 v0 = unpack2(acc[p][0]), v1 = unpack2(acc[p][1]);
        float2 v2 = unpack2(acc[p][2]), v3 = unpack2(acc[p][3]);
        float2 v4 = unpack2(acc[p][4]), v5 = unpack2(acc[p][5]);
        float2 v6 = unpack2(acc[p][6]), v7 = unpack2(acc[p][7]);
        size_t m = (size_t)m0 + ty*8 + 2*p;
        float* o0 = &out[m*DM + d0 + tx*8];
        float* o1 = &out[(m+1)*DM + d0 + tx*8];
        *(float4*)o0       = make_float4(v0.x, v1.x, v2.x, v3.x);
        *(float4*)(o0 + 4) = make_float4(v4.x, v5.x, v6.x, v7.x);
        *(float4*)o1       = make_float4(v0.y, v1.y, v2.y, v3.y);
        *(float4*)(o1 + 4) = make_float4(v4.y, v5.y, v6.y, v7.y);
    }
}

// ---------------------------------------------------------------------------
extern "C" void kernel_launch(void* const* d_in, const int* in_sizes, int n_in,
                              void* d_out, int out_size)
{
    const float* X  = (const float*)d_in[0];
    const float* Wq = (const float*)d_in[1];
    const float* Wk = (const float*)d_in[2];
    const float* Wv = (const float*)d_in[3];
    const float* Wo = (const float*)d_in[4];
    float* out = (float*)d_out;

    const int attn_smem  = 4 * 64 * 68 * (int)sizeof(float);         // ~68 KB
    const int oproj_smem = (64*68 + 64*260) * (int)sizeof(float);    // ~82 KB

    cudaFuncSetAttribute(attn_kernel,  cudaFuncAttributeMaxDynamicSharedMemorySize, attn_smem);
    cudaFuncSetAttribute(oproj_kernel, cudaFuncAttributeMaxDynamicSharedMemorySize, oproj_smem);

    qkv_kernel<<<dim3(128, 3), 128>>>(X, Wq, Wk, Wv);
    attn_kernel<<<dim3(16, 8), 256, attn_smem>>>();
    oproj_kernel<<<dim3(256, 4), 256, oproj_smem>>>(Wo, out);
}

// round 12
// speedup vs baseline: 1.0877x; 1.0246x over previous
#include <cuda_runtime.h>
#include <cstdint>

#define BB 8
#define SS 2048
#define DM 1024
#define DH 64
#define M_TOT (BB*SS)   // 16384

// Scratch (device globals — no allocations allowed)
__device__ float g_q [M_TOT*DH];
__device__ float g_k [M_TOT*DH];
__device__ float g_v [M_TOT*DH];
__device__ float g_oh[M_TOT*DH];
__device__ float g_p [2][3*M_TOT*DH];   // qkv split-K partials: [s][head][m][64]
__device__ float g_u [2][M_TOT*DH];     // attn split-KV un-normalized O partials
__device__ float g_m2[2][M_TOT];        // attn partial row max
__device__ float g_l2[2][M_TOT];        // attn partial row sum

typedef unsigned long long u64;

__device__ __forceinline__ u64 dup2(float x){
    u64 r; asm("mov.b64 %0, {%1, %1};" : "=l"(r) : "f"(x)); return r;
}
__device__ __forceinline__ u64 pack2(float a, float b){
    u64 r; asm("mov.b64 %0, {%1, %2};" : "=l"(r) : "f"(a), "f"(b)); return r;
}
__device__ __forceinline__ float2 unpack2(u64 v){
    float2 f; asm("mov.b64 {%0, %1}, %2;" : "=f"(f.x), "=f"(f.y) : "l"(v)); return f;
}
__device__ __forceinline__ void fma2(u64 &d, u64 a, u64 b){
    asm("fma.rn.f32x2 %0, %1, %2, %0;" : "+l"(d) : "l"(a), "l"(b));
}
__device__ __forceinline__ void mul2(u64 &d, u64 a){
    asm("mul.rn.f32x2 %0, %0, %1;" : "+l"(d) : "l"(a));
}

// ---------------------------------------------------------------------------
// Kernel 1: QKV projection, split-K=2.  Ypart[m,n] = sum_{d in half} X[m,d]W[n,d]
// grid = (128, 3, 2): m-block, head, k-split.  block = 128.
// BM=128, BN=64, BK=32, K-half=512.  Thread tile 8m x 8n, f32x2 packed along n.
// 768 CTAs -> 4 resident CTAs/SM => 16 warps/SM latency hiding.
// ---------------------------------------------------------------------------
__global__ __launch_bounds__(128, 4) void qkv_kernel(
    const float* __restrict__ X,
    const float* __restrict__ Wq,
    const float* __restrict__ Wk,
    const float* __restrict__ Wv)
{
    __shared__ float Xs[32*132];   // [k][m], stride 132 (528B = 33*16, aligned)
    __shared__ float Wsh[32*68];   // [k][n], stride 68  (272B = 17*16, aligned)

    const int head = blockIdx.y;
    const int z    = blockIdx.z;           // k-split index
    const float* W = (head == 0) ? Wq : ((head == 1) ? Wk : Wv);
    float* Y = g_p[z] + (size_t)head * M_TOT * DH;

    const int tid = threadIdx.x;
    const int m0  = blockIdx.x * 128;
    const int tx  = tid & 7;    // n group: n = tx*8 + (2*np + lohi)
    const int ty  = tid >> 3;   // m group: m = ty*8 + i
    const int kbase = z * 512;

    u64 acc[8][4];   // [m 0..7][n-pair 0..3], pair = (n, n+1)
    #pragma unroll
    for (int i = 0; i < 8; i++)
        #pragma unroll
        for (int j = 0; j < 4; j++) acc[i][j] = 0ULL;

    for (int kc = 0; kc < 512; kc += 32) {
        const int kk = kbase + kc;
        // X tile: 128m x 32k.  1024 float4 / 128 thr = 8 each.
        #pragma unroll
        for (int it = 0; it < 8; it++) {
            int lin = tid + it * 128;
            int k4 = lin & 7, m = lin >> 3;
            float4 v = *(const float4*)&X[(size_t)(m0 + m) * DM + kk + k4 * 4];
            Xs[(k4*4+0)*132 + m] = v.x;
            Xs[(k4*4+1)*132 + m] = v.y;
            Xs[(k4*4+2)*132 + m] = v.z;
            Xs[(k4*4+3)*132 + m] = v.w;
        }
        // W tile: 64n x 32k.  512 float4 / 128 thr = 4 each.
        #pragma unroll
        for (int it = 0; it < 4; it++) {
            int lin = tid + it * 128;
            int k4 = lin & 7, n = lin >> 3;
            float4 v = *(const float4*)&W[(size_t)n * DM + kk + k4 * 4];
            Wsh[(k4*4+0)*68 + n] = v.x;
            Wsh[(k4*4+1)*68 + n] = v.y;
            Wsh[(k4*4+2)*68 + n] = v.z;
            Wsh[(k4*4+3)*68 + n] = v.w;
        }
        __syncthreads();
        #pragma unroll 8
        for (int k = 0; k < 32; k++) {
            const u64* bp = (const u64*)&Wsh[k*68 + tx*8];
            u64 b0 = bp[0], b1 = bp[1], b2 = bp[2], b3 = bp[3];
            float4 xa = *(const float4*)&Xs[k*132 + ty*8];
            float4 xb = *(const float4*)&Xs[k*132 + ty*8 + 4];
            u64 a0 = dup2(xa.x), a1 = dup2(xa.y), a2 = dup2(xa.z), a3 = dup2(xa.w);
            u64 a4 = dup2(xb.x), a5 = dup2(xb.y), a6 = dup2(xb.z), a7 = dup2(xb.w);
            fma2(acc[0][0], a0, b0); fma2(acc[0][1], a0, b1); fma2(acc[0][2], a0, b2); fma2(acc[0][3], a0, b3);
            fma2(acc[1][0], a1, b0); fma2(acc[1][1], a1, b1); fma2(acc[1][2], a1, b2); fma2(acc[1][3], a1, b3);
            fma2(acc[2][0], a2, b0); fma2(acc[2][1], a2, b1); fma2(acc[2][2], a2, b2); fma2(acc[2][3], a2, b3);
            fma2(acc[3][0], a3, b0); fma2(acc[3][1], a3, b1); fma2(acc[3][2], a3, b2); fma2(acc[3][3], a3, b3);
            fma2(acc[4][0], a4, b0); fma2(acc[4][1], a4, b1); fma2(acc[4][2], a4, b2); fma2(acc[4][3], a4, b3);
            fma2(acc[5][0], a5, b0); fma2(acc[5][1], a5, b1); fma2(acc[5][2], a5, b2); fma2(acc[5][3], a5, b3);
            fma2(acc[6][0], a6, b0); fma2(acc[6][1], a6, b1); fma2(acc[6][2], a6, b2); fma2(acc[6][3], a6, b3);
            fma2(acc[7][0], a7, b0); fma2(acc[7][1], a7, b1); fma2(acc[7][2], a7, b2); fma2(acc[7][3], a7, b3);
        }
        __syncthreads();
    }
    #pragma unroll
    for (int i = 0; i < 8; i++) {
        float2 v0 = unpack2(acc[i][0]), v1 = unpack2(acc[i][1]);
        float2 v2 = unpack2(acc[i][2]), v3 = unpack2(acc[i][3]);
        size_t m = (size_t)m0 + ty*8 + i;
        float* yp = &Y[m*DH + tx*8];
        *(float4*)yp       = make_float4(v0.x, v0.y, v1.x, v1.y);
        *(float4*)(yp + 4) = make_float4(v2.x, v2.y, v3.x, v3.y);
    }
}

// ---------------------------------------------------------------------------
// Kernel 1b: fuse qkv split-K partials into g_q / g_k / g_v.
// ---------------------------------------------------------------------------
__global__ __launch_bounds__(256) void fuse_kernel()
{
    int f = blockIdx.x * 256 + threadIdx.x;      // float4 index
    const float4* p0 = (const float4*)g_p[0];
    const float4* p1 = (const float4*)g_p[1];
    float4 a = p0[f], b = p1[f];
    float4 r = make_float4(a.x + b.x, a.y + b.y, a.z + b.z, a.w + b.w);
    int head = f / (M_TOT * 16);                 // DH/4 = 16 float4 per row
    int rem  = f - head * (M_TOT * 16);
    float4* dst = (head == 0) ? (float4*)g_q : ((head == 1) ? (float4*)g_k : (float4*)g_v);
    dst[rem] = r;
}

// ---------------------------------------------------------------------------
// Kernel 2: causal flash attention (d=64), fp32, online softmax, split-KV=2.
// grid = (16, 8, 2), block = 256.  BQ=64, key tiles of 64.
// Block (x, b, z): q-tiles {x, 31-x}, key tiles kt ≡ z (mod 2), kt <= qt.
// Per-CTA work: z=0 -> 17, z=1 -> 16 tile-iterations (uniform).  Writes
// UN-normalized O partial + per-row (m, l); merge_kernel combines.
// ---------------------------------------------------------------------------
__global__ __launch_bounds__(256) void attn_kernel()
{
    extern __shared__ float sm[];
    float* Qs = sm;                 // [64 h][68 m]
    float* Ks = Qs + 64*68;         // [64 h][68 key]
    float* Vs = Ks + 64*68;         // [64 key][68 h]
    float* Ps = Vs + 64*68;         // [64 key][68 m]

    const int b   = blockIdx.y;
    const int z   = blockIdx.z;
    const int tid = threadIdx.x;
    const int tx  = tid & 15, ty = tid >> 4;

    const float* Qg = g_q + (size_t)b * SS * DH;
    const float* Kg = g_k + (size_t)b * SS * DH;
    const float* Vg = g_v + (size_t)b * SS * DH;
    float*       Ug = g_u[z] + (size_t)b * SS * DH;

    #pragma unroll
    for (int pass = 0; pass < 2; pass++) {
        const int qt = (pass == 0) ? (int)blockIdx.x : (31 - (int)blockIdx.x);
        const int q0 = qt * 64;

        __syncthreads();   // protect smem reuse across passes
        // Load Q tile transposed: Qs[h][m]
        #pragma unroll
        for (int i = 0; i < 4; i++) {
            int lin = tid + i * 256;
            int h4 = lin & 15, m = lin >> 4;
            float4 v = *(const float4*)&Qg[(size_t)(q0 + m) * DH + h4 * 4];
            Qs[(h4*4+0)*68 + m] = v.x;
            Qs[(h4*4+1)*68 + m] = v.y;
            Qs[(h4*4+2)*68 + m] = v.z;
            Qs[(h4*4+3)*68 + m] = v.w;
        }

        float mrow[4], lrow[4], corrv[4];
        u64 o2[2][4];
        #pragma unroll
        for (int i = 0; i < 4; i++) { mrow[i] = -1e30f; lrow[i] = 0.f; }
        #pragma unroll
        for (int i = 0; i < 2; i++)
            #pragma unroll
            for (int j = 0; j < 4; j++) o2[i][j] = 0ULL;

        // split-KV: this CTA handles key tiles kt = z, z+2, ... <= qt
        for (int kt = z; kt <= qt; kt += 2) {
            const int k0 = kt * 64;
            __syncthreads();
            // K transposed (Ks[h][key]) + V direct (Vs[key][h])
            #pragma unroll
            for (int i = 0; i < 4; i++) {
                int lin = tid + i * 256;
                int h4 = lin & 15, kk = lin >> 4;
                float4 v = *(const float4*)&Kg[(size_t)(k0 + kk) * DH + h4 * 4];
                Ks[(h4*4+0)*68 + kk] = v.x;
                Ks[(h4*4+1)*68 + kk] = v.y;
                Ks[(h4*4+2)*68 + kk] = v.z;
                Ks[(h4*4+3)*68 + kk] = v.w;
                float4 w = *(const float4*)&Vg[(size_t)(k0 + kk) * DH + h4 * 4];
                *(float4*)&Vs[kk*68 + h4*4] = w;
            }
            __syncthreads();

            // ---- S = Q K^T (reduce over h). keys: 4*tx..4*tx+3, rows: ty*4..ty*4+3
            u64 s2[2][4];
            #pragma unroll
            for (int i = 0; i < 2; i++)
                #pragma unroll
                for (int j = 0; j < 4; j++) s2[i][j] = 0ULL;
            #pragma unroll 8
            for (int h = 0; h < 64; h++) {
                const u64* qp = (const u64*)&Qs[h*68 + ty*4];
                u64 a0 = qp[0], a1 = qp[1];
                float4 kv = *(const float4*)&Ks[h*68 + tx*4];
                u64 b0 = dup2(kv.x), b1 = dup2(kv.y), b2 = dup2(kv.z), b3 = dup2(kv.w);
                fma2(s2[0][0], a0, b0); fma2(s2[0][1], a0, b1); fma2(s2[0][2], a0, b2); fma2(s2[0][3], a0, b3);
                fma2(s2[1][0], a1, b0); fma2(s2[1][1], a1, b1); fma2(s2[1][2], a1, b2); fma2(s2[1][3], a1, b3);
            }

            // unpack, scale 1/sqrt(1024), causal mask
            float p[4][4];
            #pragma unroll
            for (int i2 = 0; i2 < 2; i2++)
                #pragma unroll
                for (int j = 0; j < 4; j++) {
                    float2 v = unpack2(s2[i2][j]);
                    p[2*i2  ][j] = v.x;
                    p[2*i2+1][j] = v.y;
                }
            #pragma unroll
            for (int i = 0; i < 4; i++) {
                int q = q0 + ty*4 + i;
                #pragma unroll
                for (int j = 0; j < 4; j++) {
                    int kidx = k0 + tx*4 + j;
                    p[i][j] = (kidx <= q) ? p[i][j] * 0.03125f : -1e30f;
                }
            }

            // online softmax (row spread across 16 tx-lanes of the warp half)
            #pragma unroll
            for (int i = 0; i < 4; i++) {
                float r = fmaxf(fmaxf(p[i][0], p[i][1]), fmaxf(p[i][2], p[i][3]));
                r = fmaxf(r, __shfl_xor_sync(0xffffffffu, r, 1, 16));
                r = fmaxf(r, __shfl_xor_sync(0xffffffffu, r, 2, 16));
                r = fmaxf(r, __shfl_xor_sync(0xffffffffu, r, 4, 16));
                r = fmaxf(r, __shfl_xor_sync(0xffffffffu, r, 8, 16));
                float mnew = fmaxf(mrow[i], r);
                float corr = __expf(mrow[i] - mnew);
                mrow[i] = mnew;
                float lsum = 0.f;
                #pragma unroll
                for (int j = 0; j < 4; j++) {
                    p[i][j] = __expf(p[i][j] - mnew);
                    lsum += p[i][j];
                }
                lsum += __shfl_xor_sync(0xffffffffu, lsum, 1, 16);
                lsum += __shfl_xor_sync(0xffffffffu, lsum, 2, 16);
                lsum += __shfl_xor_sync(0xffffffffu, lsum, 4, 16);
                lsum += __shfl_xor_sync(0xffffffffu, lsum, 8, 16);
                lrow[i] = lrow[i] * corr + lsum;
                corrv[i] = corr;
            }
            // rescale O accumulators (packed pairs along m)
            #pragma unroll
            for (int i2 = 0; i2 < 2; i2++) {
                u64 c2 = pack2(corrv[2*i2], corrv[2*i2+1]);
                #pragma unroll
                for (int j = 0; j < 4; j++) mul2(o2[i2][j], c2);
            }
            // store P tile: Ps[key][m]
            #pragma unroll
            for (int i = 0; i < 4; i++) {
                int m = ty*4 + i;
                #pragma unroll
                for (int j = 0; j < 4; j++)
                    Ps[(tx*4 + j)*68 + m] = p[i][j];
            }
            __syncthreads();

            // ---- O += P V (reduce over keys) ----
            #pragma unroll 8
            for (int kk = 0; kk < 64; kk++) {
                const u64* pp = (const u64*)&Ps[kk*68 + ty*4];
                u64 a0 = pp[0], a1 = pp[1];
                float4 vv = *(const float4*)&Vs[kk*68 + tx*4];
                u64 b0 = dup2(vv.x), b1 = dup2(vv.y), b2 = dup2(vv.z), b3 = dup2(vv.w);
                fma2(o2[0][0], a0, b0); fma2(o2[0][1], a0, b1); fma2(o2[0][2], a0, b2); fma2(o2[0][3], a0, b3);
                fma2(o2[1][0], a1, b0); fma2(o2[1][1], a1, b1); fma2(o2[1][2], a1, b2); fma2(o2[1][3], a1, b3);
            }
        }

        // epilogue: write UN-normalized partial + (m, l) per row
        #pragma unroll
        for (int i2 = 0; i2 < 2; i2++) {
            float2 r0 = unpack2(o2[i2][0]), r1 = unpack2(o2[i2][1]);
            float2 r2 = unpack2(o2[i2][2]), r3 = unpack2(o2[i2][3]);
            size_t m = (size_t)q0 + ty*4 + 2*i2;
            *(float4*)&Ug[m*DH + tx*4]     = make_float4(r0.x, r1.x, r2.x, r3.x);
            *(float4*)&Ug[(m+1)*DH + tx*4] = make_float4(r0.y, r1.y, r2.y, r3.y);
        }
        if (tx == 0) {
            #pragma unroll
            for (int i = 0; i < 4; i++) {
                size_t row = (size_t)b * SS + q0 + ty*4 + i;
                g_m2[z][row] = mrow[i];
                g_l2[z][row] = lrow[i];
            }
        }
    }
}

// ---------------------------------------------------------------------------
// Kernel 2b: merge split-KV partials -> g_oh.
// grid = 1024, block = 256; one float4 (16 h-values) per thread.
// O = (U0*s0 + U1*s1) / (l0*s0 + l1*s1), s_z = e^{m_z - max(m0,m1)}.
// A partial with l <= 0 contributed no keys (z=1, qt=0 case): force s = 0.
// Every row has >= 1 valid partial (z=0 always covers kt=0), so denom > 0.
// ---------------------------------------------------------------------------
__global__ __launch_bounds__(256) void merge_kernel()
{
    int idx = blockIdx.x * 256 + threadIdx.x;    // float4 index over M_TOT*16
    int row = idx >> 4;
    float m0 = g_m2[0][row], m1 = g_m2[1][row];
    float l0 = g_l2[0][row], l1 = g_l2[1][row];
    float mm = fmaxf(m0, m1);
    float s0 = (l0 > 0.f) ? __expf(m0 - mm) : 0.f;
    float s1 = (l1 > 0.f) ? __expf(m1 - mm) : 0.f;
    float inv = 1.0f / (l0 * s0 + l1 * s1);
    float4 u0 = ((const float4*)g_u[0])[idx];
    float4 u1 = ((const float4*)g_u[1])[idx];
    float4 r;
    r.x = (u0.x * s0 + u1.x * s1) * inv;
    r.y = (u0.y * s0 + u1.y * s1) * inv;
    r.z = (u0.z * s0 + u1.z * s1) * inv;
    r.w = (u0.w * s0 + u1.w * s1) * inv;
    ((float4*)g_oh)[idx] = r;
}

// ---------------------------------------------------------------------------
// Kernel 3: output projection. out[m,d] = sum_h Oh[m,h] * Wo[d,h]
// grid = (256, 4), block = 256.  BM=64, BN=256, K=64 full.
// ---------------------------------------------------------------------------
__global__ __launch_bounds__(256) void oproj_kernel(
    const float* __restrict__ Wo, float* __restrict__ out)
{
    extern __shared__ float sm[];
    float* Os  = sm;            // [64 h][68 m]
    float* Ws2 = sm + 64*68;    // [64 h][260 d]

    const int m0 = blockIdx.x * 64;
    const int d0 = blockIdx.y * 256;
    const int tid = threadIdx.x;
    const int tx = tid & 31;    // d = d0 + tx*8 + j
    const int ty = tid >> 5;    // m = m0 + ty*8 + r

    #pragma unroll
    for (int i = 0; i < 4; i++) {
        int lin = tid + i * 256;
        int h4 = lin & 15, r = lin >> 4;
        float4 v = *(const float4*)&g_oh[(size_t)(m0 + r) * DH + h4 * 4];
        Os[(h4*4+0)*68 + r] = v.x;
        Os[(h4*4+1)*68 + r] = v.y;
        Os[(h4*4+2)*68 + r] = v.z;
        Os[(h4*4+3)*68 + r] = v.w;
    }
    #pragma unroll
    for (int i = 0; i < 16; i++) {
        int lin = tid + i * 256;
        int h4 = lin & 15, r = lin >> 4;
        float4 w = *(const float4*)&Wo[(size_t)(d0 + r) * DH + h4 * 4];
        Ws2[(h4*4+0)*260 + r] = w.x;
        Ws2[(h4*4+1)*260 + r] = w.y;
        Ws2[(h4*4+2)*260 + r] = w.z;
        Ws2[(h4*4+3)*260 + r] = w.w;
    }
    __syncthreads();

    u64 acc[4][8];
    #pragma unroll
    for (int p = 0; p < 4; p++)
        #pragma unroll
        for (int j = 0; j < 8; j++) acc[p][j] = 0ULL;

    #pragma unroll 8
    for (int h = 0; h < 64; h++) {
        const u64* op = (const u64*)&Os[h*68 + ty*8];
        u64 a0 = op[0], a1 = op[1], a2 = op[2], a3 = op[3];
        const float* wp = &Ws2[h*260 + tx*8];
        float4 w0 = *(const float4*)wp;
        float4 w1 = *(const float4*)(wp + 4);
        u64 b0 = dup2(w0.x), b1 = dup2(w0.y), b2 = dup2(w0.z), b3 = dup2(w0.w);
        u64 b4 = dup2(w1.x), b5 = dup2(w1.y), b6 = dup2(w1.z), b7 = dup2(w1.w);
        fma2(acc[0][0], a0, b0); fma2(acc[0][1], a0, b1); fma2(acc[0][2], a0, b2); fma2(acc[0][3], a0, b3);
        fma2(acc[0][4], a0, b4); fma2(acc[0][5], a0, b5); fma2(acc[0][6], a0, b6); fma2(acc[0][7], a0, b7);
        fma2(acc[1][0], a1, b0); fma2(acc[1][1], a1, b1); fma2(acc[1][2], a1, b2); fma2(acc[1][3], a1, b3);
        fma2(acc[1][4], a1, b4); fma2(acc[1][5], a1, b5); fma2(acc[1][6], a1, b6); fma2(acc[1][7], a1, b7);
        fma2(acc[2][0], a2, b0); fma2(acc[2][1], a2, b1); fma2(acc[2][2], a2, b2); fma2(acc[2][3], a2, b3);
        fma2(acc[2][4], a2, b4); fma2(acc[2][5], a2, b5); fma2(acc[2][6], a2, b6); fma2(acc[2][7], a2, b7);
        fma2(acc[3][0], a3, b0); fma2(acc[3][1], a3, b1); fma2(acc[3][2], a3, b2); fma2(acc[3][3], a3, b3);
        fma2(acc[3][4], a3, b4); fma2(acc[3][5], a3, b5); fma2(acc[3][6], a3, b6); fma2(acc[3][7], a3, b7);
    }

    #pragma unroll
    for (int p = 0; p < 4; p++) {
        float2 v0 = unpack2(acc[p][0]), v1 = unpack2(acc[p][1]);
        float2 v2 = unpack2(acc[p][2]), v3 = unpack2(acc[p][3]);
        float2 v4 = unpack2(acc[p][4]), v5 = unpack2(acc[p][5]);
        float2 v6 = unpack2(acc[p][6]), v7 = unpack2(acc[p][7]);
        size_t m = (size_t)m0 + ty*8 + 2*p;
        float* o0 = &out[m*DM + d0 + tx*8];
        float* o1 = &out[(m+1)*DM + d0 + tx*8];
        *(float4*)o0       = make_float4(v0.x, v1.x, v2.x, v3.x);
        *(float4*)(o0 + 4) = make_float4(v4.x, v5.x, v6.x, v7.x);
        *(float4*)o1       = make_float4(v0.y, v1.y, v2.y, v3.y);
        *(float4*)(o1 + 4) = make_float4(v4.y, v5.y, v6.y, v7.y);
    }
}

// ---------------------------------------------------------------------------
extern "C" void kernel_launch(void* const* d_in, const int* in_sizes, int n_in,
                              void* d_out, int out_size)
{
    const float* X  = (const float*)d_in[0];
    const float* Wq = (const float*)d_in[1];
    const float* Wk = (const float*)d_in[2];
    const float* Wv = (const float*)d_in[3];
    const float* Wo = (const float*)d_in[4];
    float* out = (float*)d_out;

    const int attn_smem  = 4 * 64 * 68 * (int)sizeof(float);         // ~68 KB
    const int oproj_smem = (64*68 + 64*260) * (int)sizeof(float);    // ~82 KB

    cudaFuncSetAttribute(attn_kernel,  cudaFuncAttributeMaxDynamicSharedMemorySize, attn_smem);
    cudaFuncSetAttribute(oproj_kernel, cudaFuncAttributeMaxDynamicSharedMemorySize, oproj_smem);

    qkv_kernel<<<dim3(128, 3, 2), 128>>>(X, Wq, Wk, Wv);
    fuse_kernel<<<3 * M_TOT * 16 / 256, 256>>>();
    attn_kernel<<<dim3(16, 8, 2), 256, attn_smem>>>();
    merge_kernel<<<M_TOT * 16 / 256, 256>>>();
    oproj_kernel<<<dim3(256, 4), 256, oproj_smem>>>(Wo, out);
}